// round 4
// baseline (speedup 1.0000x reference)
#include <cuda_runtime.h>
#include <cuda_bf16.h>

// ---------------- problem constants ----------------
#define NN    32768        // B*N nodes
#define DD    128          // D = DE = 128
#define NE    262144       // edges
#define KC    384          // 2D + DE
#define FFH   512          // feedforward hidden
#define NLAY  2

typedef unsigned long long u64;

// ---------------- scratch (static device globals; no allocation) ----------------
__device__ float g_nodes[NN * DD];     // 16 MB
__device__ float g_agg[NN * DD];       // 16 MB
__device__ float g_edge[NE * DD];      // 128 MB
__device__ float g_deg[NN];
__device__ float g_invdeg[NN];

// ---------------- packed f32x2 helpers ----------------
__device__ __forceinline__ u64 pack2(float lo, float hi) {
    u64 r; asm("mov.b64 %0, {%1,%2};" : "=l"(r) : "f"(lo), "f"(hi)); return r;
}
__device__ __forceinline__ void fma2(u64& d, u64 a, u64 b) {
    asm("fma.rn.f32x2 %0, %1, %2, %0;" : "+l"(d) : "l"(a), "l"(b));
}
__device__ __forceinline__ float2 unpack2(u64 v) {
    float2 f; asm("mov.b64 {%0,%1}, %2;" : "=f"(f.x), "=f"(f.y) : "l"(v)); return f;
}

// ---------------- weight tile stage: 32 x 128 floats, 256 threads ----------------
__device__ __forceinline__ void load_wtile(
    const float* __restrict__ Wg, int ldw, int ncol0, int kt,
    float* __restrict__ sWbuf, int tid)
{
    #pragma unroll
    for (int p = 0; p < 4; p++) {
        int fi = tid + p * 256;          // 1024 float4s = 32x128 tile
        int r = fi >> 5, c4 = fi & 31;
        *(float4*)(sWbuf + r * 128 + c4 * 4) =
            *(const float4*)(Wg + (size_t)(kt + r) * ldw + ncol0 + c4 * 4);
    }
}

// ---------------- block GEMM: [64 x K] (smem) @ [K x 128] (global, double-buffered) ----
// 256 threads: ty=tid>>4 owns rows ty*4..ty*4+3, tx=tid&15 owns cols tx*8..tx*8+7.
// acc[i][j] = packed pair (col tx*8+2j, tx*8+2j+1) for row ty*4+i.
// sW must hold 2 * 32*128 floats.
__device__ __forceinline__ void gemm_block(
    const float* __restrict__ sA, int lda, int K,
    const float* __restrict__ Wg, int ldw, int ncol0,
    float* __restrict__ sW, int tid, u64 acc[4][4])
{
    const int ty = tid >> 4, tx = tid & 15;
    const int nt = K >> 5;
    load_wtile(Wg, ldw, ncol0, 0, sW, tid);
    for (int t = 0; t < nt; t++) {
        __syncthreads();   // buf[t] visible; prior compute (reader of other buf) done
        if (t + 1 < nt)
            load_wtile(Wg, ldw, ncol0, (t + 1) << 5, sW + ((t + 1) & 1) * 4096, tid);
        const float* cw = sW + (t & 1) * 4096;
        const int kt = t << 5;
        #pragma unroll
        for (int kk = 0; kk < 32; kk += 4) {
            // one float4 activation load per row per 4 k-steps
            float4 a4[4];
            #pragma unroll
            for (int i = 0; i < 4; i++)
                a4[i] = *(const float4*)(sA + (ty * 4 + i) * lda + kt + kk);
            #pragma unroll
            for (int q = 0; q < 4; q++) {
                const float* wrow = cw + (kk + q) * 128 + tx * 8;
                u64 w0 = *(const u64*)(wrow);
                u64 w1 = *(const u64*)(wrow + 2);
                u64 w2 = *(const u64*)(wrow + 4);
                u64 w3 = *(const u64*)(wrow + 6);
                #pragma unroll
                for (int i = 0; i < 4; i++) {
                    float a = (q == 0) ? a4[i].x : (q == 1) ? a4[i].y
                             : (q == 2) ? a4[i].z : a4[i].w;
                    u64 a2 = pack2(a, a);
                    fma2(acc[i][0], a2, w0);
                    fma2(acc[i][1], a2, w1);
                    fma2(acc[i][2], a2, w2);
                    fma2(acc[i][3], a2, w3);
                }
            }
        }
    }
    __syncthreads();       // compute done before caller touches shared buffers
}

#define ZERO_ACC(acc) do { _Pragma("unroll") for (int _i = 0; _i < 4; _i++) { \
    _Pragma("unroll") for (int _j = 0; _j < 4; _j++) acc[_i][_j] = 0ull; } } while (0)

// ---------------- fused 3-layer MLP over edges ----------------
// EDGE_MODE=false: message MLP -> red.v4 scatter into agg[dst]
// EDGE_MODE=true : edge MLP   -> residual + LayerNorm, write edge_attr in place
template<bool EDGE_MODE>
__global__ __launch_bounds__(256, 1)
void mlp3_kernel(
    const float* __restrict__ nodes,
    const int*   __restrict__ ei,
    float*       __restrict__ edge_attr,
    const float* __restrict__ W0, const float* __restrict__ b0,
    const float* __restrict__ W1, const float* __restrict__ b1,
    const float* __restrict__ W2, const float* __restrict__ b2,
    const float* __restrict__ lng, const float* __restrict__ lnb,
    float*       __restrict__ agg)
{
    extern __shared__ float sh[];
    float* sA  = sh;                 // 64 x 388 (concat input, padded)
    float* sM0 = sA  + 64 * 388;     // 64 x 132
    float* sM1 = sM0 + 64 * 132;     // 64 x 132
    float* sW  = sM1 + 64 * 132;     // 2 x 32 x 128 (double buffer)
    int*   sIdx = (int*)(sW + 2 * 32 * 128);   // [0..63]=src, [64..127]=dst

    const int tid = threadIdx.x;
    const int e0  = blockIdx.x * 64;

    if (tid < 64)        sIdx[tid] = ei[e0 + tid];
    else if (tid < 128)  sIdx[tid] = ei[NE + e0 + (tid - 64)];
    __syncthreads();

    // gather concat [src | edge_attr | dst] -> sA, float4 per step
    for (int t = tid; t < 64 * 96; t += 256) {
        int r = t / 96, q = t - r * 96;
        float4 v;
        if (q < 32)      v = *(const float4*)(nodes     + (size_t)sIdx[r]      * DD + q * 4);
        else if (q < 64) v = *(const float4*)(edge_attr + (size_t)(e0 + r)     * DD + (q - 32) * 4);
        else             v = *(const float4*)(nodes     + (size_t)sIdx[64 + r] * DD + (q - 64) * 4);
        *(float4*)(sA + r * 388 + q * 4) = v;
    }

    const int ty = tid >> 4, tx = tid & 15;
    u64 acc[4][4];

    // linear0 + relu
    ZERO_ACC(acc);
    gemm_block(sA, 388, KC, W0, 128, 0, sW, tid, acc);
    {
        float2 bb[4];
        #pragma unroll
        for (int j = 0; j < 4; j++) bb[j] = *(const float2*)(b0 + tx * 8 + 2 * j);
        #pragma unroll
        for (int i = 0; i < 4; i++) {
            #pragma unroll
            for (int j = 0; j < 4; j++) {
                float2 v = unpack2(acc[i][j]);
                v.x = fmaxf(v.x + bb[j].x, 0.f);
                v.y = fmaxf(v.y + bb[j].y, 0.f);
                *(float2*)(sM0 + (ty * 4 + i) * 132 + tx * 8 + 2 * j) = v;
            }
        }
    }
    // linear1 + relu
    ZERO_ACC(acc);
    gemm_block(sM0, 132, DD, W1, 128, 0, sW, tid, acc);
    {
        float2 bb[4];
        #pragma unroll
        for (int j = 0; j < 4; j++) bb[j] = *(const float2*)(b1 + tx * 8 + 2 * j);
        #pragma unroll
        for (int i = 0; i < 4; i++) {
            #pragma unroll
            for (int j = 0; j < 4; j++) {
                float2 v = unpack2(acc[i][j]);
                v.x = fmaxf(v.x + bb[j].x, 0.f);
                v.y = fmaxf(v.y + bb[j].y, 0.f);
                *(float2*)(sM1 + (ty * 4 + i) * 132 + tx * 8 + 2 * j) = v;
            }
        }
    }
    // linear2
    ZERO_ACC(acc);
    gemm_block(sM1, 132, DD, W2, 128, 0, sW, tid, acc);

    float2 bb[4];
    #pragma unroll
    for (int j = 0; j < 4; j++) bb[j] = *(const float2*)(b2 + tx * 8 + 2 * j);

    if (!EDGE_MODE) {
        // scatter-add messages into agg[dst]
        #pragma unroll
        for (int i = 0; i < 4; i++) {
            int r = ty * 4 + i;
            int dst = sIdx[64 + r];
            float* base = agg + (size_t)dst * DD + tx * 8;
            float2 v0 = unpack2(acc[i][0]); v0.x += bb[0].x; v0.y += bb[0].y;
            float2 v1 = unpack2(acc[i][1]); v1.x += bb[1].x; v1.y += bb[1].y;
            float2 v2 = unpack2(acc[i][2]); v2.x += bb[2].x; v2.y += bb[2].y;
            float2 v3 = unpack2(acc[i][3]); v3.x += bb[3].x; v3.y += bb[3].y;
            asm volatile("red.global.add.v4.f32 [%0], {%1,%2,%3,%4};"
                         :: "l"(base), "f"(v0.x), "f"(v0.y), "f"(v1.x), "f"(v1.y) : "memory");
            asm volatile("red.global.add.v4.f32 [%0], {%1,%2,%3,%4};"
                         :: "l"(base + 4), "f"(v2.x), "f"(v2.y), "f"(v3.x), "f"(v3.y) : "memory");
        }
    } else {
        // residual (edge_attr slice of sA) + bias -> sM0, then row LayerNorm -> edge_attr
        #pragma unroll
        for (int i = 0; i < 4; i++) {
            int r = ty * 4 + i;
            #pragma unroll
            for (int j = 0; j < 4; j++) {
                int c = tx * 8 + 2 * j;
                float2 v = unpack2(acc[i][j]);
                v.x += bb[j].x + sA[r * 388 + 128 + c];
                v.y += bb[j].y + sA[r * 388 + 128 + c + 1];
                *(float2*)(sM0 + r * 132 + c) = v;
            }
        }
        __syncthreads();
        int w = tid >> 5, lane = tid & 31;
        float4 gg = *(const float4*)(lng + lane * 4);
        float4 gb = *(const float4*)(lnb + lane * 4);
        for (int r = w; r < 64; r += 8) {
            float4 v = *(float4*)(sM0 + r * 132 + lane * 4);
            float s1 = v.x + v.y + v.z + v.w;
            float s2 = v.x * v.x + v.y * v.y + v.z * v.z + v.w * v.w;
            #pragma unroll
            for (int o = 16; o > 0; o >>= 1) {
                s1 += __shfl_xor_sync(0xffffffffu, s1, o);
                s2 += __shfl_xor_sync(0xffffffffu, s2, o);
            }
            float mean = s1 * (1.f / 128.f);
            float var  = s2 * (1.f / 128.f) - mean * mean;
            float rstd = rsqrtf(var + 1e-5f);
            float4 o4;
            o4.x = (v.x - mean) * rstd * gg.x + gb.x;
            o4.y = (v.y - mean) * rstd * gg.y + gb.y;
            o4.z = (v.z - mean) * rstd * gg.z + gb.z;
            o4.w = (v.w - mean) * rstd * gg.w + gb.w;
            *(float4*)(edge_attr + (size_t)(e0 + r) * DD + lane * 4) = o4;
        }
    }
}

// ---------------- feedforward + residual + LN over 64-node tiles ----------------
__global__ __launch_bounds__(256, 1)
void ff_kernel(float* __restrict__ nodes,
               const float* __restrict__ W0, const float* __restrict__ b0,
               const float* __restrict__ W1, const float* __restrict__ b1,
               const float* __restrict__ lng, const float* __restrict__ lnb)
{
    extern __shared__ float sh[];
    float* sX = sh;               // 64 x 132
    float* sH = sX + 64 * 132;    // 64 x 516
    float* sW = sH + 64 * 516;    // 2 x 32 x 128 (double buffer)

    const int tid = threadIdx.x;
    const int n0  = blockIdx.x * 64;

    for (int t = tid; t < 64 * 32; t += 256) {
        int r = t >> 5, q = t & 31;
        *(float4*)(sX + r * 132 + q * 4) = *(const float4*)(nodes + (size_t)(n0 + r) * DD + q * 4);
    }

    const int ty = tid >> 4, tx = tid & 15;
    u64 acc[4][4];

    // hidden = relu(x @ W0 + b0), computed in 4 column chunks of 128
    for (int ch = 0; ch < 4; ch++) {
        ZERO_ACC(acc);
        gemm_block(sX, 132, DD, W0, FFH, ch * 128, sW, tid, acc);
        float2 bb[4];
        #pragma unroll
        for (int j = 0; j < 4; j++) bb[j] = *(const float2*)(b0 + ch * 128 + tx * 8 + 2 * j);
        #pragma unroll
        for (int i = 0; i < 4; i++) {
            #pragma unroll
            for (int j = 0; j < 4; j++) {
                float2 v = unpack2(acc[i][j]);
                v.x = fmaxf(v.x + bb[j].x, 0.f);
                v.y = fmaxf(v.y + bb[j].y, 0.f);
                *(float2*)(sH + (ty * 4 + i) * 516 + ch * 128 + tx * 8 + 2 * j) = v;
            }
        }
    }
    // out = hidden @ W1 + b1 + residual
    ZERO_ACC(acc);
    gemm_block(sH, 516, FFH, W1, 128, 0, sW, tid, acc);
    {
        float2 bb[4];
        #pragma unroll
        for (int j = 0; j < 4; j++) bb[j] = *(const float2*)(b1 + tx * 8 + 2 * j);
        #pragma unroll
        for (int i = 0; i < 4; i++) {
            int r = ty * 4 + i;
            #pragma unroll
            for (int j = 0; j < 4; j++) {
                int c = tx * 8 + 2 * j;
                float2 v = unpack2(acc[i][j]);
                v.x += bb[j].x + sX[r * 132 + c];
                v.y += bb[j].y + sX[r * 132 + c + 1];
                *(float2*)(sX + r * 132 + c) = v;
            }
        }
    }
    __syncthreads();
    // row LayerNorm
    int w = tid >> 5, lane = tid & 31;
    float4 gg = *(const float4*)(lng + lane * 4);
    float4 gb = *(const float4*)(lnb + lane * 4);
    for (int r = w; r < 64; r += 8) {
        float4 v = *(float4*)(sX + r * 132 + lane * 4);
        float s1 = v.x + v.y + v.z + v.w;
        float s2 = v.x * v.x + v.y * v.y + v.z * v.z + v.w * v.w;
        #pragma unroll
        for (int o = 16; o > 0; o >>= 1) {
            s1 += __shfl_xor_sync(0xffffffffu, s1, o);
            s2 += __shfl_xor_sync(0xffffffffu, s2, o);
        }
        float mean = s1 * (1.f / 128.f);
        float var  = s2 * (1.f / 128.f) - mean * mean;
        float rstd = rsqrtf(var + 1e-5f);
        float4 o4;
        o4.x = (v.x - mean) * rstd * gg.x + gb.x;
        o4.y = (v.y - mean) * rstd * gg.y + gb.y;
        o4.z = (v.z - mean) * rstd * gg.z + gb.z;
        o4.w = (v.w - mean) * rstd * gg.w + gb.w;
        *(float4*)(nodes + (size_t)(n0 + r) * DD + lane * 4) = o4;
    }
}

// ---------------- node update: nodes = LN(nodes + agg * inv_deg) ----------------
__global__ void node_ln_kernel(float* __restrict__ nodes,
                               const float* __restrict__ agg,
                               const float* __restrict__ invdeg,
                               const float* __restrict__ lng,
                               const float* __restrict__ lnb)
{
    int gwarp = (blockIdx.x * blockDim.x + threadIdx.x) >> 5;
    int lane  = threadIdx.x & 31;
    if (gwarp >= NN) return;
    float id = invdeg[gwarp];
    float4 x = *(const float4*)(nodes + (size_t)gwarp * DD + lane * 4);
    float4 a = *(const float4*)(agg   + (size_t)gwarp * DD + lane * 4);
    float4 v = {x.x + a.x * id, x.y + a.y * id, x.z + a.z * id, x.w + a.w * id};
    float s1 = v.x + v.y + v.z + v.w;
    float s2 = v.x * v.x + v.y * v.y + v.z * v.z + v.w * v.w;
    #pragma unroll
    for (int o = 16; o > 0; o >>= 1) {
        s1 += __shfl_xor_sync(0xffffffffu, s1, o);
        s2 += __shfl_xor_sync(0xffffffffu, s2, o);
    }
    float mean = s1 * (1.f / 128.f);
    float var  = s2 * (1.f / 128.f) - mean * mean;
    float rstd = rsqrtf(var + 1e-5f);
    float4 gg = *(const float4*)(lng + lane * 4);
    float4 gb = *(const float4*)(lnb + lane * 4);
    float4 o4;
    o4.x = (v.x - mean) * rstd * gg.x + gb.x;
    o4.y = (v.y - mean) * rstd * gg.y + gb.y;
    o4.z = (v.z - mean) * rstd * gg.z + gb.z;
    o4.w = (v.w - mean) * rstd * gg.w + gb.w;
    *(float4*)(nodes + (size_t)gwarp * DD + lane * 4) = o4;
}

// ---------------- tiny utility kernels ----------------
__global__ void zero_kernel(float* p, int n4) {   // n4 = count of float4
    int i = blockIdx.x * blockDim.x + threadIdx.x;
    if (i < n4) ((float4*)p)[i] = make_float4(0.f, 0.f, 0.f, 0.f);
}
__global__ void deg_kernel(const int* __restrict__ ei, float* __restrict__ deg) {
    int e = blockIdx.x * blockDim.x + threadIdx.x;
    if (e < NE) atomicAdd(&deg[ei[NE + e]], 1.0f);
}
__global__ void invdeg_kernel(const float* __restrict__ deg, float* __restrict__ invdeg) {
    int i = blockIdx.x * blockDim.x + threadIdx.x;
    if (i < NN) invdeg[i] = 1.0f / fmaxf(deg[i], 1.0f);
}

// ---------------- host launch ----------------
#define SMEM_MLP ((64 * 388 + 2 * 64 * 132 + 2 * 32 * 128) * 4 + 128 * 4)
#define SMEM_FF  ((64 * 132 + 64 * 516 + 2 * 32 * 128) * 4)

extern "C" void kernel_launch(void* const* d_in, const int* in_sizes, int n_in,
                              void* d_out, int out_size)
{
    const float* x    = (const float*)d_in[0];
    const int*   ei   = (const int*)d_in[1];
    const float* ea   = (const float*)d_in[2];
    const float* mW0  = (const float*)d_in[3];
    const float* mb0  = (const float*)d_in[4];
    const float* mW1  = (const float*)d_in[5];
    const float* mb1  = (const float*)d_in[6];
    const float* mW2  = (const float*)d_in[7];
    const float* mb2  = (const float*)d_in[8];
    const float* n0g  = (const float*)d_in[9];
    const float* n0b  = (const float*)d_in[10];
    const float* fW0  = (const float*)d_in[11];
    const float* fb0  = (const float*)d_in[12];
    const float* fW1  = (const float*)d_in[13];
    const float* fb1  = (const float*)d_in[14];
    const float* n1g  = (const float*)d_in[15];
    const float* n1b  = (const float*)d_in[16];
    const float* eW0  = (const float*)d_in[17];
    const float* eb0  = (const float*)d_in[18];
    const float* eW1  = (const float*)d_in[19];
    const float* eb1  = (const float*)d_in[20];
    const float* eW2  = (const float*)d_in[21];
    const float* eb2  = (const float*)d_in[22];
    const float* eng  = (const float*)d_in[23];
    const float* enb  = (const float*)d_in[24];

    float *nodes, *agg, *edge, *deg, *invdeg;
    cudaGetSymbolAddress((void**)&nodes,  g_nodes);
    cudaGetSymbolAddress((void**)&agg,    g_agg);
    cudaGetSymbolAddress((void**)&edge,   g_edge);
    cudaGetSymbolAddress((void**)&deg,    g_deg);
    cudaGetSymbolAddress((void**)&invdeg, g_invdeg);

    cudaFuncSetAttribute(mlp3_kernel<false>, cudaFuncAttributeMaxDynamicSharedMemorySize, SMEM_MLP);
    cudaFuncSetAttribute(mlp3_kernel<true>,  cudaFuncAttributeMaxDynamicSharedMemorySize, SMEM_MLP);
    cudaFuncSetAttribute(ff_kernel,          cudaFuncAttributeMaxDynamicSharedMemorySize, SMEM_FF);

    // init mutable state (replay-safe: re-init every launch)
    cudaMemcpyAsync(nodes, x,  (size_t)NN * DD * 4, cudaMemcpyDeviceToDevice);
    cudaMemcpyAsync(edge,  ea, (size_t)NE * DD * 4, cudaMemcpyDeviceToDevice);

    zero_kernel<<<(NN / 4 + 255) / 256, 256>>>(deg, NN / 4);
    deg_kernel<<<(NE + 255) / 256, 256>>>(ei, deg);
    invdeg_kernel<<<(NN + 255) / 256, 256>>>(deg, invdeg);

    const int MLP_BLOCKS = NE / 64;     // 4096
    const int FF_BLOCKS  = NN / 64;     // 512
    const int LN_BLOCKS  = NN * 32 / 256;

    for (int l = 0; l < NLAY; l++) {
        zero_kernel<<<(NN * DD / 4 + 255) / 256, 256>>>(agg, NN * DD / 4);
        mlp3_kernel<false><<<MLP_BLOCKS, 256, SMEM_MLP>>>(
            nodes, ei, edge,
            mW0 + (size_t)l * KC * DD,  mb0 + l * DD,
            mW1 + (size_t)l * DD * DD,  mb1 + l * DD,
            mW2 + (size_t)l * DD * DD,  mb2 + l * DD,
            nullptr, nullptr, agg);
        node_ln_kernel<<<LN_BLOCKS, 256>>>(nodes, agg, invdeg, n0g + l * DD, n0b + l * DD);
        ff_kernel<<<FF_BLOCKS, 256, SMEM_FF>>>(
            nodes,
            fW0 + (size_t)l * DD * FFH, fb0 + l * FFH,
            fW1 + (size_t)l * FFH * DD, fb1 + l * DD,
            n1g + l * DD, n1b + l * DD);
        mlp3_kernel<true><<<MLP_BLOCKS, 256, SMEM_MLP>>>(
            nodes, ei, edge,
            eW0 + (size_t)l * KC * DD,  eb0 + l * DD,
            eW1 + (size_t)l * DD * DD,  eb1 + l * DD,
            eW2 + (size_t)l * DD * DD,  eb2 + l * DD,
            eng + l * DD, enb + l * DD, nullptr);
    }

    cudaMemcpyAsync(d_out, nodes, (size_t)NN * DD * 4, cudaMemcpyDeviceToDevice);
}

// round 12
// speedup vs baseline: 1.5912x; 1.5912x over previous
#include <cuda_runtime.h>
#include <cuda_bf16.h>

// ---------------- problem constants ----------------
#define NN    32768        // B*N nodes
#define DD    128          // D = DE = 128
#define NE    262144       // edges
#define FFH   512          // feedforward hidden
#define NLAY  2

typedef unsigned long long u64;

// ---------------- scratch (static device globals; no allocation) ----------------
__device__ float g_nodes[NN * DD];     // 16 MB
__device__ float g_agg[NN * DD];       // 16 MB
__device__ float g_edge[NE * DD];      // 128 MB
__device__ float g_deg[NN];

// ---------------- packed f32x2 helpers ----------------
__device__ __forceinline__ u64 pack2(float lo, float hi) {
    u64 r; asm("mov.b64 %0, {%1,%2};" : "=l"(r) : "f"(lo), "f"(hi)); return r;
}
__device__ __forceinline__ void fma2(u64& d, u64 a, u64 b) {
    asm("fma.rn.f32x2 %0, %1, %2, %0;" : "+l"(d) : "l"(a), "l"(b));
}
__device__ __forceinline__ float2 unpack2(u64 v) {
    float2 f; asm("mov.b64 {%0,%1}, %2;" : "=f"(f.x), "=f"(f.y) : "l"(v)); return f;
}

// ---------------- weight tile stage: 32 x 128 floats, 256 threads ----------------
__device__ __forceinline__ void load_wtile(
    const float* __restrict__ Wg, int ldw, int ncol0, int kt,
    float* __restrict__ sWbuf, int tid)
{
    #pragma unroll
    for (int p = 0; p < 4; p++) {
        int fi = tid + p * 256;          // 1024 float4s = 32x128 tile
        int r = fi >> 5, c4 = fi & 31;
        *(float4*)(sWbuf + r * 128 + c4 * 4) =
            *(const float4*)(Wg + (size_t)(kt + r) * ldw + ncol0 + c4 * 4);
    }
}

// ---------------- block GEMM: [R*16 x K] (smem) @ [K x 128] (streamed, dbuf) ----------
// 256 threads: ty=tid>>4 owns rows ty*R..ty*R+R-1.
// tx=tid&15 owns cols {tx*4..tx*4+3} and {64+tx*4..64+tx*4+3}  (conflict-free LDS.128)
// acc[i][0..1] = pairs of first group, acc[i][2..3] = pairs of second group.
// sW must hold 2 * 32*128 floats. acc NOT zeroed here (accumulate across calls).
template<int R>
__device__ __forceinline__ void gemm_block(
    const float* __restrict__ sA, int lda, int K,
    const float* __restrict__ Wg, int ldw, int ncol0,
    float* __restrict__ sW, int tid, u64 acc[R][4])
{
    const int ty = tid >> 4, tx = tid & 15;
    const int nt = K >> 5;
    load_wtile(Wg, ldw, ncol0, 0, sW, tid);
    for (int t = 0; t < nt; t++) {
        __syncthreads();   // buf[t] visible; prior compute (reader of other buf) done
        if (t + 1 < nt)
            load_wtile(Wg, ldw, ncol0, (t + 1) << 5, sW + ((t + 1) & 1) * 4096, tid);
        const float* cw = sW + (t & 1) * 4096;
        const int kt = t << 5;
        #pragma unroll 2
        for (int kk = 0; kk < 32; kk += 4) {
            float4 a4[R];
            #pragma unroll
            for (int i = 0; i < R; i++)
                a4[i] = *(const float4*)(sA + (ty * R + i) * lda + kt + kk);
            #pragma unroll
            for (int q = 0; q < 4; q++) {
                const float* wrow = cw + (kk + q) * 128;
                ulonglong2 wA = *(const ulonglong2*)(wrow + tx * 4);
                ulonglong2 wB = *(const ulonglong2*)(wrow + 64 + tx * 4);
                #pragma unroll
                for (int i = 0; i < R; i++) {
                    float a = (q == 0) ? a4[i].x : (q == 1) ? a4[i].y
                             : (q == 2) ? a4[i].z : a4[i].w;
                    u64 a2 = pack2(a, a);
                    fma2(acc[i][0], a2, wA.x);
                    fma2(acc[i][1], a2, wA.y);
                    fma2(acc[i][2], a2, wB.x);
                    fma2(acc[i][3], a2, wB.y);
                }
            }
        }
    }
    __syncthreads();       // compute done before caller touches shared buffers
}

#define ZERO_ACC(acc, R) do { _Pragma("unroll") for (int _i = 0; _i < R; _i++) { \
    _Pragma("unroll") for (int _j = 0; _j < 4; _j++) acc[_i][_j] = 0ull; } } while (0)

// epilogue helper: acc + bias (+optional relu) -> float4 pair for row i
__device__ __forceinline__ void acc_row(const u64 a[4], float4 ba, float4 bb,
                                        bool relu, float4& o0, float4& o1)
{
    float2 v0 = unpack2(a[0]), v1 = unpack2(a[1]), v2 = unpack2(a[2]), v3 = unpack2(a[3]);
    o0.x = v0.x + ba.x; o0.y = v0.y + ba.y; o0.z = v1.x + ba.z; o0.w = v1.y + ba.w;
    o1.x = v2.x + bb.x; o1.y = v2.y + bb.y; o1.z = v3.x + bb.z; o1.w = v3.y + bb.w;
    if (relu) {
        o0.x = fmaxf(o0.x, 0.f); o0.y = fmaxf(o0.y, 0.f);
        o0.z = fmaxf(o0.z, 0.f); o0.w = fmaxf(o0.w, 0.f);
        o1.x = fmaxf(o1.x, 0.f); o1.y = fmaxf(o1.y, 0.f);
        o1.z = fmaxf(o1.z, 0.f); o1.w = fmaxf(o1.w, 0.f);
    }
}

// ---------------- fused 3-layer MLP over 128-edge tiles ----------------
// EDGE_MODE=false: message MLP -> red.v4 scatter into agg[dst]
// EDGE_MODE=true : edge MLP   -> residual + LayerNorm, write edge_attr in place
template<bool EDGE_MODE>
__global__ __launch_bounds__(256, 1)
void mlp3_kernel(
    const float* __restrict__ nodes,
    const int*   __restrict__ ei,
    float*       __restrict__ edge_attr,
    const float* __restrict__ W0, const float* __restrict__ b0,
    const float* __restrict__ W1, const float* __restrict__ b1,
    const float* __restrict__ W2, const float* __restrict__ b2,
    const float* __restrict__ lng, const float* __restrict__ lnb,
    float*       __restrict__ agg)
{
    extern __shared__ float sh[];
    float* sBuf = sh;                  // 128 x 132 (input segment / GEMM1 output)
    float* sM0  = sBuf + 128 * 132;    // 128 x 132 (GEMM0 output)
    float* sW   = sM0  + 128 * 132;    // 2 x 32 x 128 (double buffer)
    int*   sIdx = (int*)(sW + 2 * 32 * 128);   // [0..127]=src, [128..255]=dst

    const int tid = threadIdx.x;
    const int e0  = blockIdx.x * 128;
    const int ty = tid >> 4, tx = tid & 15;

    if (tid < 128) sIdx[tid] = ei[e0 + tid];
    else           sIdx[tid] = ei[NE + e0 + (tid - 128)];
    __syncthreads();

    u64 acc[8][4];

    // ---- GEMM0: K=384 streamed as 3 gathered 128x128 segments ----
    ZERO_ACC(acc, 8);
    #pragma unroll 1
    for (int seg = 0; seg < 3; seg++) {
        for (int t = tid; t < 128 * 32; t += 256) {
            int r = t >> 5, q = t & 31;
            float4 v;
            if (seg == 0)      v = *(const float4*)(nodes + (size_t)sIdx[r] * DD + q * 4);
            else if (seg == 1) v = *(const float4*)(edge_attr + (size_t)(e0 + r) * DD + q * 4);
            else               v = *(const float4*)(nodes + (size_t)sIdx[128 + r] * DD + q * 4);
            *(float4*)(sBuf + r * 132 + q * 4) = v;
        }
        // gemm_block's first internal __syncthreads makes gather visible
        gemm_block<8>(sBuf, 132, 128, W0 + (size_t)seg * 128 * 128, 128, 0, sW, tid, acc);
    }
    // relu + bias -> sM0
    {
        float4 ba = *(const float4*)(b0 + tx * 4);
        float4 bb = *(const float4*)(b0 + 64 + tx * 4);
        #pragma unroll
        for (int i = 0; i < 8; i++) {
            int r = ty * 8 + i;
            float4 o0, o1; acc_row(acc[i], ba, bb, true, o0, o1);
            *(float4*)(sM0 + r * 132 + tx * 4) = o0;
            *(float4*)(sM0 + r * 132 + 64 + tx * 4) = o1;
        }
    }
    // ---- GEMM1 ----
    ZERO_ACC(acc, 8);
    gemm_block<8>(sM0, 132, 128, W1, 128, 0, sW, tid, acc);
    {
        float4 ba = *(const float4*)(b1 + tx * 4);
        float4 bb = *(const float4*)(b1 + 64 + tx * 4);
        #pragma unroll
        for (int i = 0; i < 8; i++) {
            int r = ty * 8 + i;
            float4 o0, o1; acc_row(acc[i], ba, bb, true, o0, o1);
            *(float4*)(sBuf + r * 132 + tx * 4) = o0;
            *(float4*)(sBuf + r * 132 + 64 + tx * 4) = o1;
        }
    }
    // ---- GEMM2 ----
    ZERO_ACC(acc, 8);
    gemm_block<8>(sBuf, 132, 128, W2, 128, 0, sW, tid, acc);

    float4 ba = *(const float4*)(b2 + tx * 4);
    float4 bb = *(const float4*)(b2 + 64 + tx * 4);

    if (!EDGE_MODE) {
        // scatter-add messages into agg[dst]
        #pragma unroll
        for (int i = 0; i < 8; i++) {
            int r = ty * 8 + i;
            float* base = agg + (size_t)sIdx[128 + r] * DD;
            float4 o0, o1; acc_row(acc[i], ba, bb, false, o0, o1);
            asm volatile("red.global.add.v4.f32 [%0], {%1,%2,%3,%4};"
                         :: "l"(base + tx * 4), "f"(o0.x), "f"(o0.y), "f"(o0.z), "f"(o0.w)
                         : "memory");
            asm volatile("red.global.add.v4.f32 [%0], {%1,%2,%3,%4};"
                         :: "l"(base + 64 + tx * 4), "f"(o1.x), "f"(o1.y), "f"(o1.z), "f"(o1.w)
                         : "memory");
        }
    } else {
        // pre-LN values -> sBuf (safe: gemm_block ended with barrier)
        #pragma unroll
        for (int i = 0; i < 8; i++) {
            int r = ty * 8 + i;
            float4 o0, o1; acc_row(acc[i], ba, bb, false, o0, o1);
            *(float4*)(sBuf + r * 132 + tx * 4) = o0;
            *(float4*)(sBuf + r * 132 + 64 + tx * 4) = o1;
        }
        __syncthreads();
        int w = tid >> 5, lane = tid & 31;
        float4 gg = *(const float4*)(lng + lane * 4);
        float4 gb = *(const float4*)(lnb + lane * 4);
        for (int r = w; r < 128; r += 8) {
            float4 v = *(float4*)(sBuf + r * 132 + lane * 4);
            float4 e = *(const float4*)(edge_attr + (size_t)(e0 + r) * DD + lane * 4);
            v.x += e.x; v.y += e.y; v.z += e.z; v.w += e.w;   // residual
            float s1 = v.x + v.y + v.z + v.w;
            float s2 = v.x * v.x + v.y * v.y + v.z * v.z + v.w * v.w;
            #pragma unroll
            for (int o = 16; o > 0; o >>= 1) {
                s1 += __shfl_xor_sync(0xffffffffu, s1, o);
                s2 += __shfl_xor_sync(0xffffffffu, s2, o);
            }
            float mean = s1 * (1.f / 128.f);
            float var  = s2 * (1.f / 128.f) - mean * mean;
            float rstd = rsqrtf(var + 1e-5f);
            float4 o4;
            o4.x = (v.x - mean) * rstd * gg.x + gb.x;
            o4.y = (v.y - mean) * rstd * gg.y + gb.y;
            o4.z = (v.z - mean) * rstd * gg.z + gb.z;
            o4.w = (v.w - mean) * rstd * gg.w + gb.w;
            *(float4*)(edge_attr + (size_t)(e0 + r) * DD + lane * 4) = o4;
        }
    }
}

// ---------------- feedforward + residual + LN over 64-node tiles (R=4) ----------
__global__ __launch_bounds__(256, 1)
void ff_kernel(float* __restrict__ nodes,
               const float* __restrict__ W0, const float* __restrict__ b0,
               const float* __restrict__ W1, const float* __restrict__ b1,
               const float* __restrict__ lng, const float* __restrict__ lnb)
{
    extern __shared__ float sh[];
    float* sX = sh;               // 64 x 132
    float* sH = sX + 64 * 132;    // 64 x 516
    float* sW = sH + 64 * 516;    // 2 x 32 x 128 (double buffer)

    const int tid = threadIdx.x;
    const int n0  = blockIdx.x * 64;
    const int ty = tid >> 4, tx = tid & 15;

    for (int t = tid; t < 64 * 32; t += 256) {
        int r = t >> 5, q = t & 31;
        *(float4*)(sX + r * 132 + q * 4) = *(const float4*)(nodes + (size_t)(n0 + r) * DD + q * 4);
    }

    u64 acc[4][4];

    // hidden = relu(x @ W0 + b0), in 4 column chunks of 128
    #pragma unroll 1
    for (int ch = 0; ch < 4; ch++) {
        ZERO_ACC(acc, 4);
        gemm_block<4>(sX, 132, 128, W0, FFH, ch * 128, sW, tid, acc);
        float4 ba = *(const float4*)(b0 + ch * 128 + tx * 4);
        float4 bb = *(const float4*)(b0 + ch * 128 + 64 + tx * 4);
        #pragma unroll
        for (int i = 0; i < 4; i++) {
            int r = ty * 4 + i;
            float4 o0, o1; acc_row(acc[i], ba, bb, true, o0, o1);
            *(float4*)(sH + r * 516 + ch * 128 + tx * 4) = o0;
            *(float4*)(sH + r * 516 + ch * 128 + 64 + tx * 4) = o1;
        }
    }
    // out = hidden @ W1 + b1 + residual -> sX
    ZERO_ACC(acc, 4);
    gemm_block<4>(sH, 516, FFH, W1, 128, 0, sW, tid, acc);
    {
        float4 ba = *(const float4*)(b1 + tx * 4);
        float4 bb = *(const float4*)(b1 + 64 + tx * 4);
        #pragma unroll
        for (int i = 0; i < 4; i++) {
            int r = ty * 4 + i;
            float4 o0, o1; acc_row(acc[i], ba, bb, false, o0, o1);
            float4 x0 = *(float4*)(sX + r * 132 + tx * 4);
            float4 x1 = *(float4*)(sX + r * 132 + 64 + tx * 4);
            o0.x += x0.x; o0.y += x0.y; o0.z += x0.z; o0.w += x0.w;
            o1.x += x1.x; o1.y += x1.y; o1.z += x1.z; o1.w += x1.w;
            *(float4*)(sX + r * 132 + tx * 4) = o0;
            *(float4*)(sX + r * 132 + 64 + tx * 4) = o1;
        }
    }
    __syncthreads();
    // row LayerNorm
    int w = tid >> 5, lane = tid & 31;
    float4 gg = *(const float4*)(lng + lane * 4);
    float4 gb = *(const float4*)(lnb + lane * 4);
    for (int r = w; r < 64; r += 8) {
        float4 v = *(float4*)(sX + r * 132 + lane * 4);
        float s1 = v.x + v.y + v.z + v.w;
        float s2 = v.x * v.x + v.y * v.y + v.z * v.z + v.w * v.w;
        #pragma unroll
        for (int o = 16; o > 0; o >>= 1) {
            s1 += __shfl_xor_sync(0xffffffffu, s1, o);
            s2 += __shfl_xor_sync(0xffffffffu, s2, o);
        }
        float mean = s1 * (1.f / 128.f);
        float var  = s2 * (1.f / 128.f) - mean * mean;
        float rstd = rsqrtf(var + 1e-5f);
        float4 o4;
        o4.x = (v.x - mean) * rstd * gg.x + gb.x;
        o4.y = (v.y - mean) * rstd * gg.y + gb.y;
        o4.z = (v.z - mean) * rstd * gg.z + gb.z;
        o4.w = (v.w - mean) * rstd * gg.w + gb.w;
        *(float4*)(nodes + (size_t)(n0 + r) * DD + lane * 4) = o4;
    }
}

// ---------------- node update: nodes = LN(nodes + agg/deg); re-zero agg --------
__global__ void node_ln_kernel(float* __restrict__ nodes,
                               float* __restrict__ agg,
                               const float* __restrict__ deg,
                               const float* __restrict__ lng,
                               const float* __restrict__ lnb)
{
    int gwarp = (blockIdx.x * blockDim.x + threadIdx.x) >> 5;
    int lane  = threadIdx.x & 31;
    if (gwarp >= NN) return;
    float id = 1.0f / fmaxf(deg[gwarp], 1.0f);
    float4 x = *(const float4*)(nodes + (size_t)gwarp * DD + lane * 4);
    float4 a = *(const float4*)(agg   + (size_t)gwarp * DD + lane * 4);
    // re-zero agg for the next layer's scatter
    *(float4*)(agg + (size_t)gwarp * DD + lane * 4) = make_float4(0.f, 0.f, 0.f, 0.f);
    float4 v = {x.x + a.x * id, x.y + a.y * id, x.z + a.z * id, x.w + a.w * id};
    float s1 = v.x + v.y + v.z + v.w;
    float s2 = v.x * v.x + v.y * v.y + v.z * v.z + v.w * v.w;
    #pragma unroll
    for (int o = 16; o > 0; o >>= 1) {
        s1 += __shfl_xor_sync(0xffffffffu, s1, o);
        s2 += __shfl_xor_sync(0xffffffffu, s2, o);
    }
    float mean = s1 * (1.f / 128.f);
    float var  = s2 * (1.f / 128.f) - mean * mean;
    float rstd = rsqrtf(var + 1e-5f);
    float4 gg = *(const float4*)(lng + lane * 4);
    float4 gb = *(const float4*)(lnb + lane * 4);
    float4 o4;
    o4.x = (v.x - mean) * rstd * gg.x + gb.x;
    o4.y = (v.y - mean) * rstd * gg.y + gb.y;
    o4.z = (v.z - mean) * rstd * gg.z + gb.z;
    o4.w = (v.w - mean) * rstd * gg.w + gb.w;
    *(float4*)(nodes + (size_t)gwarp * DD + lane * 4) = o4;
}

// ---------------- setup kernels ----------------
__global__ void zero_all_kernel(float* __restrict__ agg, float* __restrict__ deg) {
    int i = blockIdx.x * blockDim.x + threadIdx.x;
    int nagg4 = NN * DD / 4;
    if (i < nagg4) ((float4*)agg)[i] = make_float4(0.f, 0.f, 0.f, 0.f);
    else if (i < nagg4 + NN / 4) ((float4*)deg)[i - nagg4] = make_float4(0.f, 0.f, 0.f, 0.f);
}
__global__ void deg_kernel(const int* __restrict__ ei, float* __restrict__ deg) {
    int e = blockIdx.x * blockDim.x + threadIdx.x;
    if (e < NE) atomicAdd(&deg[ei[NE + e]], 1.0f);
}

// ---------------- host launch ----------------
#define SMEM_MLP ((2 * 128 * 132 + 2 * 32 * 128) * 4 + 256 * 4)
#define SMEM_FF  ((64 * 132 + 64 * 516 + 2 * 32 * 128) * 4)

extern "C" void kernel_launch(void* const* d_in, const int* in_sizes, int n_in,
                              void* d_out, int out_size)
{
    const float* x    = (const float*)d_in[0];
    const int*   ei   = (const int*)d_in[1];
    const float* ea   = (const float*)d_in[2];
    const float* mW0  = (const float*)d_in[3];
    const float* mb0  = (const float*)d_in[4];
    const float* mW1  = (const float*)d_in[5];
    const float* mb1  = (const float*)d_in[6];
    const float* mW2  = (const float*)d_in[7];
    const float* mb2  = (const float*)d_in[8];
    const float* n0g  = (const float*)d_in[9];
    const float* n0b  = (const float*)d_in[10];
    const float* fW0  = (const float*)d_in[11];
    const float* fb0  = (const float*)d_in[12];
    const float* fW1  = (const float*)d_in[13];
    const float* fb1  = (const float*)d_in[14];
    const float* n1g  = (const float*)d_in[15];
    const float* n1b  = (const float*)d_in[16];
    const float* eW0  = (const float*)d_in[17];
    const float* eb0  = (const float*)d_in[18];
    const float* eW1  = (const float*)d_in[19];
    const float* eb1  = (const float*)d_in[20];
    const float* eW2  = (const float*)d_in[21];
    const float* eb2  = (const float*)d_in[22];
    const float* eng  = (const float*)d_in[23];
    const float* enb  = (const float*)d_in[24];

    float *nodes, *agg, *edge, *deg;
    cudaGetSymbolAddress((void**)&nodes, g_nodes);
    cudaGetSymbolAddress((void**)&agg,   g_agg);
    cudaGetSymbolAddress((void**)&edge,  g_edge);
    cudaGetSymbolAddress((void**)&deg,   g_deg);

    cudaFuncSetAttribute(mlp3_kernel<false>, cudaFuncAttributeMaxDynamicSharedMemorySize, SMEM_MLP);
    cudaFuncSetAttribute(mlp3_kernel<true>,  cudaFuncAttributeMaxDynamicSharedMemorySize, SMEM_MLP);
    cudaFuncSetAttribute(ff_kernel,          cudaFuncAttributeMaxDynamicSharedMemorySize, SMEM_FF);

    // init mutable state (replay-safe: re-init every launch)
    cudaMemcpyAsync(nodes, x,  (size_t)NN * DD * 4, cudaMemcpyDeviceToDevice);
    cudaMemcpyAsync(edge,  ea, (size_t)NE * DD * 4, cudaMemcpyDeviceToDevice);

    // kernel launch order matters for ncu (-s 5 -c 1 lands on launch idx 5 = mlp3<true>)
    zero_all_kernel<<<(NN * DD / 4 + NN / 4 + 255) / 256, 256>>>(agg, deg);   // idx 0
    deg_kernel<<<(NE + 255) / 256, 256>>>(ei, deg);                           // idx 1

    const int MLP_BLOCKS = NE / 128;    // 2048
    const int FF_BLOCKS  = NN / 64;     // 512
    const int LN_BLOCKS  = NN * 32 / 256;

    for (int l = 0; l < NLAY; l++) {
        mlp3_kernel<false><<<MLP_BLOCKS, 256, SMEM_MLP>>>(                    // idx 2 / 6
            nodes, ei, edge,
            mW0 + (size_t)l * 384 * DD, mb0 + l * DD,
            mW1 + (size_t)l * DD * DD,  mb1 + l * DD,
            mW2 + (size_t)l * DD * DD,  mb2 + l * DD,
            nullptr, nullptr, agg);
        node_ln_kernel<<<LN_BLOCKS, 256>>>(nodes, agg, deg,                   // idx 3 / 7
                                           n0g + l * DD, n0b + l * DD);
        ff_kernel<<<FF_BLOCKS, 256, SMEM_FF>>>(                               // idx 4 / 8
            nodes,
            fW0 + (size_t)l * DD * FFH, fb0 + l * FFH,
            fW1 + (size_t)l * FFH * DD, fb1 + l * DD,
            n1g + l * DD, n1b + l * DD);
        mlp3_kernel<true><<<MLP_BLOCKS, 256, SMEM_MLP>>>(                     // idx 5 / 9
            nodes, ei, edge,
            eW0 + (size_t)l * 384 * DD, eb0 + l * DD,
            eW1 + (size_t)l * DD * DD,  eb1 + l * DD,
            eW2 + (size_t)l * DD * DD,  eb2 + l * DD,
            eng + l * DD, enb + l * DD, nullptr);
    }

    cudaMemcpyAsync(d_out, nodes, (size_t)NN * DD * 4, cudaMemcpyDeviceToDevice);
}

// round 15
// speedup vs baseline: 1.6806x; 1.0562x over previous
#include <cuda_runtime.h>
#include <cuda_bf16.h>

// ---------------- problem constants ----------------
#define NN    32768        // B*N nodes
#define DD    128          // D = DE = 128
#define NE    262144       // edges
#define FFH   512          // feedforward hidden
#define NLAY  2

typedef unsigned long long u64;

// ---------------- scratch (static device globals; no allocation) ----------------
__device__ float g_nodes[NN * DD];     // 16 MB
__device__ float g_agg[NN * DD];       // 16 MB
__device__ float g_edge[NE * DD];      // 128 MB
__device__ float g_deg[NN];

// ---------------- packed f32x2 helpers ----------------
__device__ __forceinline__ u64 pack2(float lo, float hi) {
    u64 r; asm("mov.b64 %0, {%1,%2};" : "=l"(r) : "f"(lo), "f"(hi)); return r;
}
__device__ __forceinline__ void fma2(u64& d, u64 a, u64 b) {
    asm("fma.rn.f32x2 %0, %1, %2, %0;" : "+l"(d) : "l"(a), "l"(b));
}
__device__ __forceinline__ float2 unpack2(u64 v) {
    float2 f; asm("mov.b64 {%0,%1}, %2;" : "=f"(f.x), "=f"(f.y) : "l"(v)); return f;
}

// ---------------- async weight tile stage: 32 x 128 floats, 256 threads ----------
// cp.async.cg 16B each: fire-and-forget, no producer stall.
__device__ __forceinline__ void load_wtile_async(
    const float* __restrict__ Wg, int ldw, int ncol0, int kt,
    unsigned swb_buf, int tid)
{
    #pragma unroll
    for (int p = 0; p < 4; p++) {
        int fi = tid + p * 256;          // 1024 float4s = 32x128 tile
        int r = fi >> 5, c4 = fi & 31;
        asm volatile("cp.async.cg.shared.global [%0], [%1], 16;"
            :: "r"(swb_buf + (unsigned)(r * 128 + c4 * 4) * 4u),
               "l"(Wg + (size_t)(kt + r) * ldw + ncol0 + c4 * 4)
            : "memory");
    }
}
#define CPASYNC_COMMIT() asm volatile("cp.async.commit_group;" ::: "memory")
#define CPASYNC_WAIT0()  asm volatile("cp.async.wait_group 0;" ::: "memory")

// ---------------- block GEMM: [R*16 x K] (smem) @ [K x 128] (cp.async dbuf) --------
// 256 threads: ty=tid>>4 owns rows ty*R..ty*R+R-1.
// tx=tid&15 owns cols {tx*4..tx*4+3} and {64+tx*4..64+tx*4+3}  (conflict-free LDS.128)
// sW must hold 2 * 32*128 floats. acc NOT zeroed here (accumulate across calls).
// Pipeline: exactly one cp.async group in flight; prefetch issued AFTER the tile-top
// barrier (all readers of the target buffer are done), so it overlaps compute(t).
template<int R>
__device__ __forceinline__ void gemm_block(
    const float* __restrict__ sA, int lda, int K,
    const float* __restrict__ Wg, int ldw, int ncol0,
    float* __restrict__ sW, int tid, u64 acc[R][4])
{
    const int ty = tid >> 4, tx = tid & 15;
    const int nt = K >> 5;
    const unsigned swb = (unsigned)__cvta_generic_to_shared(sW);
    load_wtile_async(Wg, ldw, ncol0, 0, swb, tid);
    CPASYNC_COMMIT();
    for (int t = 0; t < nt; t++) {
        CPASYNC_WAIT0();     // tile t landed (this thread's group)
        __syncthreads();     // all threads' groups landed; prior compute done
        if (t + 1 < nt) {    // safe: buffer (t+1)&1's readers (compute t-1) are past barrier
            load_wtile_async(Wg, ldw, ncol0, (t + 1) << 5,
                             swb + (unsigned)(((t + 1) & 1) * 16384), tid);
            CPASYNC_COMMIT();
        }
        const float* cw = sW + (t & 1) * 4096;
        const int kt = t << 5;
        #pragma unroll 2
        for (int kk = 0; kk < 32; kk += 4) {
            float4 a4[R];
            #pragma unroll
            for (int i = 0; i < R; i++)
                a4[i] = *(const float4*)(sA + (ty * R + i) * lda + kt + kk);
            #pragma unroll
            for (int q = 0; q < 4; q++) {
                const float* wrow = cw + (kk + q) * 128;
                ulonglong2 wA = *(const ulonglong2*)(wrow + tx * 4);
                ulonglong2 wB = *(const ulonglong2*)(wrow + 64 + tx * 4);
                #pragma unroll
                for (int i = 0; i < R; i++) {
                    float a = (q == 0) ? a4[i].x : (q == 1) ? a4[i].y
                             : (q == 2) ? a4[i].z : a4[i].w;
                    u64 a2 = pack2(a, a);
                    fma2(acc[i][0], a2, wA.x);
                    fma2(acc[i][1], a2, wA.y);
                    fma2(acc[i][2], a2, wB.x);
                    fma2(acc[i][3], a2, wB.y);
                }
            }
        }
    }
    __syncthreads();       // compute done before caller touches shared buffers
}

#define ZERO_ACC(acc, R) do { _Pragma("unroll") for (int _i = 0; _i < R; _i++) { \
    _Pragma("unroll") for (int _j = 0; _j < 4; _j++) acc[_i][_j] = 0ull; } } while (0)

// epilogue helper: acc + bias (+optional relu) -> float4 pair for row i
__device__ __forceinline__ void acc_row(const u64 a[4], float4 ba, float4 bb,
                                        bool relu, float4& o0, float4& o1)
{
    float2 v0 = unpack2(a[0]), v1 = unpack2(a[1]), v2 = unpack2(a[2]), v3 = unpack2(a[3]);
    o0.x = v0.x + ba.x; o0.y = v0.y + ba.y; o0.z = v1.x + ba.z; o0.w = v1.y + ba.w;
    o1.x = v2.x + bb.x; o1.y = v2.y + bb.y; o1.z = v3.x + bb.z; o1.w = v3.y + bb.w;
    if (relu) {
        o0.x = fmaxf(o0.x, 0.f); o0.y = fmaxf(o0.y, 0.f);
        o0.z = fmaxf(o0.z, 0.f); o0.w = fmaxf(o0.w, 0.f);
        o1.x = fmaxf(o1.x, 0.f); o1.y = fmaxf(o1.y, 0.f);
        o1.z = fmaxf(o1.z, 0.f); o1.w = fmaxf(o1.w, 0.f);
    }
}

// ---------------- fused 3-layer MLP over 128-edge tiles ----------------
// EDGE_MODE=false: message MLP -> red.v4 scatter into agg[dst]
// EDGE_MODE=true : edge MLP   -> residual + LayerNorm, write edge_attr in place
template<bool EDGE_MODE>
__global__ __launch_bounds__(256, 1)
void mlp3_kernel(
    const float* __restrict__ nodes,
    const int*   __restrict__ ei,
    float*       __restrict__ edge_attr,
    const float* __restrict__ W0, const float* __restrict__ b0,
    const float* __restrict__ W1, const float* __restrict__ b1,
    const float* __restrict__ W2, const float* __restrict__ b2,
    const float* __restrict__ lng, const float* __restrict__ lnb,
    float*       __restrict__ agg)
{
    extern __shared__ float sh[];
    float* sBuf = sh;                  // 128 x 132 (input segment / GEMM1 output)
    float* sM0  = sBuf + 128 * 132;    // 128 x 132 (GEMM0 output)
    float* sW   = sM0  + 128 * 132;    // 2 x 32 x 128 (cp.async double buffer)
    int*   sIdx = (int*)(sW + 2 * 32 * 128);   // [0..127]=src, [128..255]=dst

    const int tid = threadIdx.x;
    const int e0  = blockIdx.x * 128;
    const int ty = tid >> 4, tx = tid & 15;

    if (tid < 128) sIdx[tid] = ei[e0 + tid];
    else           sIdx[tid] = ei[NE + e0 + (tid - 128)];
    __syncthreads();

    u64 acc[8][4];

    // ---- GEMM0: K=384 streamed as 3 gathered 128x128 segments ----
    ZERO_ACC(acc, 8);
    #pragma unroll 1
    for (int seg = 0; seg < 3; seg++) {
        for (int t = tid; t < 128 * 32; t += 256) {
            int r = t >> 5, q = t & 31;
            float4 v;
            if (seg == 0)      v = *(const float4*)(nodes + (size_t)sIdx[r] * DD + q * 4);
            else if (seg == 1) v = *(const float4*)(edge_attr + (size_t)(e0 + r) * DD + q * 4);
            else               v = *(const float4*)(nodes + (size_t)sIdx[128 + r] * DD + q * 4);
            *(float4*)(sBuf + r * 132 + q * 4) = v;
        }
        // gemm_block's first internal __syncthreads makes gather visible
        gemm_block<8>(sBuf, 132, 128, W0 + (size_t)seg * 128 * 128, 128, 0, sW, tid, acc);
    }
    // relu + bias -> sM0
    {
        float4 ba = *(const float4*)(b0 + tx * 4);
        float4 bb = *(const float4*)(b0 + 64 + tx * 4);
        #pragma unroll
        for (int i = 0; i < 8; i++) {
            int r = ty * 8 + i;
            float4 o0, o1; acc_row(acc[i], ba, bb, true, o0, o1);
            *(float4*)(sM0 + r * 132 + tx * 4) = o0;
            *(float4*)(sM0 + r * 132 + 64 + tx * 4) = o1;
        }
    }
    // ---- GEMM1 ----
    ZERO_ACC(acc, 8);
    gemm_block<8>(sM0, 132, 128, W1, 128, 0, sW, tid, acc);
    {
        float4 ba = *(const float4*)(b1 + tx * 4);
        float4 bb = *(const float4*)(b1 + 64 + tx * 4);
        #pragma unroll
        for (int i = 0; i < 8; i++) {
            int r = ty * 8 + i;
            float4 o0, o1; acc_row(acc[i], ba, bb, true, o0, o1);
            *(float4*)(sBuf + r * 132 + tx * 4) = o0;
            *(float4*)(sBuf + r * 132 + 64 + tx * 4) = o1;
        }
    }
    // ---- GEMM2 ----
    ZERO_ACC(acc, 8);
    gemm_block<8>(sBuf, 132, 128, W2, 128, 0, sW, tid, acc);

    float4 ba = *(const float4*)(b2 + tx * 4);
    float4 bb = *(const float4*)(b2 + 64 + tx * 4);

    if (!EDGE_MODE) {
        // scatter-add messages into agg[dst]
        #pragma unroll
        for (int i = 0; i < 8; i++) {
            int r = ty * 8 + i;
            float* base = agg + (size_t)sIdx[128 + r] * DD;
            float4 o0, o1; acc_row(acc[i], ba, bb, false, o0, o1);
            asm volatile("red.global.add.v4.f32 [%0], {%1,%2,%3,%4};"
                         :: "l"(base + tx * 4), "f"(o0.x), "f"(o0.y), "f"(o0.z), "f"(o0.w)
                         : "memory");
            asm volatile("red.global.add.v4.f32 [%0], {%1,%2,%3,%4};"
                         :: "l"(base + 64 + tx * 4), "f"(o1.x), "f"(o1.y), "f"(o1.z), "f"(o1.w)
                         : "memory");
        }
    } else {
        // pre-LN values -> sBuf (safe: gemm_block ended with barrier)
        #pragma unroll
        for (int i = 0; i < 8; i++) {
            int r = ty * 8 + i;
            float4 o0, o1; acc_row(acc[i], ba, bb, false, o0, o1);
            *(float4*)(sBuf + r * 132 + tx * 4) = o0;
            *(float4*)(sBuf + r * 132 + 64 + tx * 4) = o1;
        }
        __syncthreads();
        int w = tid >> 5, lane = tid & 31;
        float4 gg = *(const float4*)(lng + lane * 4);
        float4 gb = *(const float4*)(lnb + lane * 4);
        for (int r = w; r < 128; r += 8) {
            float4 v = *(float4*)(sBuf + r * 132 + lane * 4);
            float4 e = *(const float4*)(edge_attr + (size_t)(e0 + r) * DD + lane * 4);
            v.x += e.x; v.y += e.y; v.z += e.z; v.w += e.w;   // residual
            float s1 = v.x + v.y + v.z + v.w;
            float s2 = v.x * v.x + v.y * v.y + v.z * v.z + v.w * v.w;
            #pragma unroll
            for (int o = 16; o > 0; o >>= 1) {
                s1 += __shfl_xor_sync(0xffffffffu, s1, o);
                s2 += __shfl_xor_sync(0xffffffffu, s2, o);
            }
            float mean = s1 * (1.f / 128.f);
            float var  = s2 * (1.f / 128.f) - mean * mean;
            float rstd = rsqrtf(var + 1e-5f);
            float4 o4;
            o4.x = (v.x - mean) * rstd * gg.x + gb.x;
            o4.y = (v.y - mean) * rstd * gg.y + gb.y;
            o4.z = (v.z - mean) * rstd * gg.z + gb.z;
            o4.w = (v.w - mean) * rstd * gg.w + gb.w;
            *(float4*)(edge_attr + (size_t)(e0 + r) * DD + lane * 4) = o4;
        }
    }
}

// ---------------- feedforward + residual + LN over 64-node tiles (R=4) ----------
__global__ __launch_bounds__(256, 1)
void ff_kernel(float* __restrict__ nodes,
               const float* __restrict__ W0, const float* __restrict__ b0,
               const float* __restrict__ W1, const float* __restrict__ b1,
               const float* __restrict__ lng, const float* __restrict__ lnb)
{
    extern __shared__ float sh[];
    float* sX = sh;               // 64 x 132
    float* sH = sX + 64 * 132;    // 64 x 516
    float* sW = sH + 64 * 516;    // 2 x 32 x 128 (cp.async double buffer)

    const int tid = threadIdx.x;
    const int n0  = blockIdx.x * 64;
    const int ty = tid >> 4, tx = tid & 15;

    for (int t = tid; t < 64 * 32; t += 256) {
        int r = t >> 5, q = t & 31;
        *(float4*)(sX + r * 132 + q * 4) = *(const float4*)(nodes + (size_t)(n0 + r) * DD + q * 4);
    }

    u64 acc[4][4];

    // hidden = relu(x @ W0 + b0), in 4 column chunks of 128
    #pragma unroll 1
    for (int ch = 0; ch < 4; ch++) {
        ZERO_ACC(acc, 4);
        gemm_block<4>(sX, 132, 128, W0, FFH, ch * 128, sW, tid, acc);
        float4 ba = *(const float4*)(b0 + ch * 128 + tx * 4);
        float4 bb = *(const float4*)(b0 + ch * 128 + 64 + tx * 4);
        #pragma unroll
        for (int i = 0; i < 4; i++) {
            int r = ty * 4 + i;
            float4 o0, o1; acc_row(acc[i], ba, bb, true, o0, o1);
            *(float4*)(sH + r * 516 + ch * 128 + tx * 4) = o0;
            *(float4*)(sH + r * 516 + ch * 128 + 64 + tx * 4) = o1;
        }
    }
    // out = hidden @ W1 + b1 + residual -> sX
    ZERO_ACC(acc, 4);
    gemm_block<4>(sH, 516, FFH, W1, 128, 0, sW, tid, acc);
    {
        float4 ba = *(const float4*)(b1 + tx * 4);
        float4 bb = *(const float4*)(b1 + 64 + tx * 4);
        #pragma unroll
        for (int i = 0; i < 4; i++) {
            int r = ty * 4 + i;
            float4 o0, o1; acc_row(acc[i], ba, bb, false, o0, o1);
            float4 x0 = *(float4*)(sX + r * 132 + tx * 4);
            float4 x1 = *(float4*)(sX + r * 132 + 64 + tx * 4);
            o0.x += x0.x; o0.y += x0.y; o0.z += x0.z; o0.w += x0.w;
            o1.x += x1.x; o1.y += x1.y; o1.z += x1.z; o1.w += x1.w;
            *(float4*)(sX + r * 132 + tx * 4) = o0;
            *(float4*)(sX + r * 132 + 64 + tx * 4) = o1;
        }
    }
    __syncthreads();
    // row LayerNorm
    int w = tid >> 5, lane = tid & 31;
    float4 gg = *(const float4*)(lng + lane * 4);
    float4 gb = *(const float4*)(lnb + lane * 4);
    for (int r = w; r < 64; r += 8) {
        float4 v = *(float4*)(sX + r * 132 + lane * 4);
        float s1 = v.x + v.y + v.z + v.w;
        float s2 = v.x * v.x + v.y * v.y + v.z * v.z + v.w * v.w;
        #pragma unroll
        for (int o = 16; o > 0; o >>= 1) {
            s1 += __shfl_xor_sync(0xffffffffu, s1, o);
            s2 += __shfl_xor_sync(0xffffffffu, s2, o);
        }
        float mean = s1 * (1.f / 128.f);
        float var  = s2 * (1.f / 128.f) - mean * mean;
        float rstd = rsqrtf(var + 1e-5f);
        float4 o4;
        o4.x = (v.x - mean) * rstd * gg.x + gb.x;
        o4.y = (v.y - mean) * rstd * gg.y + gb.y;
        o4.z = (v.z - mean) * rstd * gg.z + gb.z;
        o4.w = (v.w - mean) * rstd * gg.w + gb.w;
        *(float4*)(nodes + (size_t)(n0 + r) * DD + lane * 4) = o4;
    }
}

// ---------------- node update: nodes = LN(nodes + agg/deg); re-zero agg --------
__global__ void node_ln_kernel(float* __restrict__ nodes,
                               float* __restrict__ agg,
                               const float* __restrict__ deg,
                               const float* __restrict__ lng,
                               const float* __restrict__ lnb)
{
    int gwarp = (blockIdx.x * blockDim.x + threadIdx.x) >> 5;
    int lane  = threadIdx.x & 31;
    if (gwarp >= NN) return;
    float id = 1.0f / fmaxf(deg[gwarp], 1.0f);
    float4 x = *(const float4*)(nodes + (size_t)gwarp * DD + lane * 4);
    float4 a = *(const float4*)(agg   + (size_t)gwarp * DD + lane * 4);
    // re-zero agg for the next layer's scatter
    *(float4*)(agg + (size_t)gwarp * DD + lane * 4) = make_float4(0.f, 0.f, 0.f, 0.f);
    float4 v = {x.x + a.x * id, x.y + a.y * id, x.z + a.z * id, x.w + a.w * id};
    float s1 = v.x + v.y + v.z + v.w;
    float s2 = v.x * v.x + v.y * v.y + v.z * v.z + v.w * v.w;
    #pragma unroll
    for (int o = 16; o > 0; o >>= 1) {
        s1 += __shfl_xor_sync(0xffffffffu, s1, o);
        s2 += __shfl_xor_sync(0xffffffffu, s2, o);
    }
    float mean = s1 * (1.f / 128.f);
    float var  = s2 * (1.f / 128.f) - mean * mean;
    float rstd = rsqrtf(var + 1e-5f);
    float4 gg = *(const float4*)(lng + lane * 4);
    float4 gb = *(const float4*)(lnb + lane * 4);
    float4 o4;
    o4.x = (v.x - mean) * rstd * gg.x + gb.x;
    o4.y = (v.y - mean) * rstd * gg.y + gb.y;
    o4.z = (v.z - mean) * rstd * gg.z + gb.z;
    o4.w = (v.w - mean) * rstd * gg.w + gb.w;
    *(float4*)(nodes + (size_t)gwarp * DD + lane * 4) = o4;
}

// ---------------- setup kernels (two launches: aligns ncu -s 5 onto mlp3) -------
__global__ void zero_agg_kernel(float* __restrict__ agg) {
    int i = blockIdx.x * blockDim.x + threadIdx.x;
    if (i < NN * DD / 4) ((float4*)agg)[i] = make_float4(0.f, 0.f, 0.f, 0.f);
}
__global__ void zero_deg_kernel(float* __restrict__ deg) {
    int i = blockIdx.x * blockDim.x + threadIdx.x;
    if (i < NN / 4) ((float4*)deg)[i] = make_float4(0.f, 0.f, 0.f, 0.f);
}
__global__ void deg_kernel(const int* __restrict__ ei, float* __restrict__ deg) {
    int e = blockIdx.x * blockDim.x + threadIdx.x;
    if (e < NE) atomicAdd(&deg[ei[NE + e]], 1.0f);
}

// ---------------- host launch ----------------
#define SMEM_MLP ((2 * 128 * 132 + 2 * 32 * 128) * 4 + 256 * 4)
#define SMEM_FF  ((64 * 132 + 64 * 516 + 2 * 32 * 128) * 4)

extern "C" void kernel_launch(void* const* d_in, const int* in_sizes, int n_in,
                              void* d_out, int out_size)
{
    const float* x    = (const float*)d_in[0];
    const int*   ei   = (const int*)d_in[1];
    const float* ea   = (const float*)d_in[2];
    const float* mW0  = (const float*)d_in[3];
    const float* mb0  = (const float*)d_in[4];
    const float* mW1  = (const float*)d_in[5];
    const float* mb1  = (const float*)d_in[6];
    const float* mW2  = (const float*)d_in[7];
    const float* mb2  = (const float*)d_in[8];
    const float* n0g  = (const float*)d_in[9];
    const float* n0b  = (const float*)d_in[10];
    const float* fW0  = (const float*)d_in[11];
    const float* fb0  = (const float*)d_in[12];
    const float* fW1  = (const float*)d_in[13];
    const float* fb1  = (const float*)d_in[14];
    const float* n1g  = (const float*)d_in[15];
    const float* n1b  = (const float*)d_in[16];
    const float* eW0  = (const float*)d_in[17];
    const float* eb0  = (const float*)d_in[18];
    const float* eW1  = (const float*)d_in[19];
    const float* eb1  = (const float*)d_in[20];
    const float* eW2  = (const float*)d_in[21];
    const float* eb2  = (const float*)d_in[22];
    const float* eng  = (const float*)d_in[23];
    const float* enb  = (const float*)d_in[24];

    float *nodes, *agg, *edge, *deg;
    cudaGetSymbolAddress((void**)&nodes, g_nodes);
    cudaGetSymbolAddress((void**)&agg,   g_agg);
    cudaGetSymbolAddress((void**)&edge,  g_edge);
    cudaGetSymbolAddress((void**)&deg,   g_deg);

    cudaFuncSetAttribute(mlp3_kernel<false>, cudaFuncAttributeMaxDynamicSharedMemorySize, SMEM_MLP);
    cudaFuncSetAttribute(mlp3_kernel<true>,  cudaFuncAttributeMaxDynamicSharedMemorySize, SMEM_MLP);
    cudaFuncSetAttribute(ff_kernel,          cudaFuncAttributeMaxDynamicSharedMemorySize, SMEM_FF);

    // init mutable state (replay-safe: re-init every launch)
    cudaMemcpyAsync(nodes, x,  (size_t)NN * DD * 4, cudaMemcpyDeviceToDevice);   // act 0
    cudaMemcpyAsync(edge,  ea, (size_t)NE * DD * 4, cudaMemcpyDeviceToDevice);   // act 1

    zero_agg_kernel<<<(NN * DD / 4 + 255) / 256, 256>>>(agg);                    // act 2
    zero_deg_kernel<<<(NN / 4 + 255) / 256, 256>>>(deg);                         // act 3
    deg_kernel<<<(NE + 255) / 256, 256>>>(ei, deg);                              // act 4

    const int MLP_BLOCKS = NE / 128;    // 2048
    const int FF_BLOCKS  = NN / 64;     // 512
    const int LN_BLOCKS  = NN * 32 / 256;

    for (int l = 0; l < NLAY; l++) {
        mlp3_kernel<false><<<MLP_BLOCKS, 256, SMEM_MLP>>>(                       // act 5 (ncu)
            nodes, ei, edge,
            mW0 + (size_t)l * 384 * DD, mb0 + l * DD,
            mW1 + (size_t)l * DD * DD,  mb1 + l * DD,
            mW2 + (size_t)l * DD * DD,  mb2 + l * DD,
            nullptr, nullptr, agg);
        node_ln_kernel<<<LN_BLOCKS, 256>>>(nodes, agg, deg,
                                           n0g + l * DD, n0b + l * DD);
        ff_kernel<<<FF_BLOCKS, 256, SMEM_FF>>>(
            nodes,
            fW0 + (size_t)l * DD * FFH, fb0 + l * FFH,
            fW1 + (size_t)l * FFH * DD, fb1 + l * DD,
            n1g + l * DD, n1b + l * DD);
        mlp3_kernel<true><<<MLP_BLOCKS, 256, SMEM_MLP>>>(
            nodes, ei, edge,
            eW0 + (size_t)l * 384 * DD, eb0 + l * DD,
            eW1 + (size_t)l * DD * DD,  eb1 + l * DD,
            eW2 + (size_t)l * DD * DD,  eb2 + l * DD,
            eng + l * DD, enb + l * DD, nullptr);
    }

    cudaMemcpyAsync(d_out, nodes, (size_t)NN * DD * 4, cudaMemcpyDeviceToDevice);
}